// round 2
// baseline (speedup 1.0000x reference)
#include <cuda_runtime.h>

#define NUM_GRAPHS 1024

// Scratch (device globals — no allocations allowed)
__device__ float g_S[NUM_GRAPHS * 3];     // sum q_i * r_i per graph
__device__ float g_R[NUM_GRAPHS * 3];     // sum r_i per graph
__device__ float g_sumq;                  // global sum of q
__device__ int   g_off[NUM_GRAPHS + 1];   // segment offsets

// ---------------------------------------------------------------------------
// Kernel 1: dtype-agnostic segment boundaries from the sorted batch array.
//
// The reference asks for int64 but JAX may silently deliver int32. Detection:
// view the buffer as int32 words. A sorted int32 label array is nondecreasing;
// a small-valued int64 array viewed as int32 alternates value,0,value,0 and is
// strictly decreasing near the tail (…1023,0,1023,0). Scan a tail window.
//
// Single block of 1024 threads: thread 0 detects, __syncthreads, then every
// thread g binary-searches offsets[g] = first i with batch[i] >= g.
// ---------------------------------------------------------------------------
__global__ __launch_bounds__(1024) void boundaries_kernel(const void* __restrict__ batch_raw,
                                                          int n) {
    __shared__ int sh_is64;
    const int* b32 = (const int*)batch_raw;

    if (threadIdx.x == 0) {
        // n int32 words are safely readable under either true dtype
        // (int64 array of n elems has 2n words; int32 array has n words).
        int is64 = 0;
        int lo_w = (n > 64) ? (n - 64) : 0;
        int prev = b32[lo_w];
        for (int w = lo_w + 1; w < n; ++w) {
            int cur = b32[w];
            if (cur < prev) { is64 = 1; break; }
            prev = cur;
        }
        sh_is64 = is64;
        g_sumq = 0.0f;
        g_off[NUM_GRAPHS] = n;
    }
    __syncthreads();

    const int is64 = sh_is64;
    const long long* b64 = (const long long*)batch_raw;

    int g = threadIdx.x;          // 0..1023
    int target = g;
    int lo = 0, hi = n;
    if (is64) {
        long long t = (long long)target;
        while (lo < hi) {
            int mid = (int)(((unsigned)lo + (unsigned)hi) >> 1);
            if (b64[mid] < t) lo = mid + 1; else hi = mid;
        }
    } else {
        while (lo < hi) {
            int mid = (int)(((unsigned)lo + (unsigned)hi) >> 1);
            if (b32[mid] < target) lo = mid + 1; else hi = mid;
        }
    }
    g_off[g] = lo;
}

// ---------------------------------------------------------------------------
// Kernel 2: one block per graph. Streams positions+q for its contiguous
// segment, block-reduces 7 accumulators, writes S/R directly (no atomics),
// one atomicAdd per block for the global q sum.
// ---------------------------------------------------------------------------
__global__ __launch_bounds__(256) void polar_main_kernel(
    const float* __restrict__ pos,   // [N,3]
    const float* __restrict__ q)     // [N]
{
    const int g     = blockIdx.x;
    const int start = g_off[g];
    const int end   = g_off[g + 1];
    const int tid   = threadIdx.x;

    float sx = 0.f, sy = 0.f, sz = 0.f;
    float rx = 0.f, ry = 0.f, rz = 0.f;
    float qs = 0.f;

    const float3* __restrict__ pos3 = (const float3*)pos;
    for (int i = start + tid; i < end; i += 256) {
        float  qi = q[i];
        float3 p  = pos3[i];
        sx = fmaf(qi, p.x, sx);
        sy = fmaf(qi, p.y, sy);
        sz = fmaf(qi, p.z, sz);
        rx += p.x; ry += p.y; rz += p.z;
        qs += qi;
    }

    // Block reduction of 7 floats: warp shuffle, then cross-warp via shared.
    __shared__ float sh[8][7];
    const unsigned FULL = 0xFFFFFFFFu;
    #pragma unroll
    for (int off = 16; off > 0; off >>= 1) {
        sx += __shfl_down_sync(FULL, sx, off);
        sy += __shfl_down_sync(FULL, sy, off);
        sz += __shfl_down_sync(FULL, sz, off);
        rx += __shfl_down_sync(FULL, rx, off);
        ry += __shfl_down_sync(FULL, ry, off);
        rz += __shfl_down_sync(FULL, rz, off);
        qs += __shfl_down_sync(FULL, qs, off);
    }
    int wid = tid >> 5, lid = tid & 31;
    if (lid == 0) {
        sh[wid][0] = sx; sh[wid][1] = sy; sh[wid][2] = sz;
        sh[wid][3] = rx; sh[wid][4] = ry; sh[wid][5] = rz;
        sh[wid][6] = qs;
    }
    __syncthreads();
    if (wid == 0) {
        float v0 = (lid < 8) ? sh[lid][0] : 0.f;
        float v1 = (lid < 8) ? sh[lid][1] : 0.f;
        float v2 = (lid < 8) ? sh[lid][2] : 0.f;
        float v3 = (lid < 8) ? sh[lid][3] : 0.f;
        float v4 = (lid < 8) ? sh[lid][4] : 0.f;
        float v5 = (lid < 8) ? sh[lid][5] : 0.f;
        float v6 = (lid < 8) ? sh[lid][6] : 0.f;
        #pragma unroll
        for (int off = 4; off > 0; off >>= 1) {
            v0 += __shfl_down_sync(FULL, v0, off);
            v1 += __shfl_down_sync(FULL, v1, off);
            v2 += __shfl_down_sync(FULL, v2, off);
            v3 += __shfl_down_sync(FULL, v3, off);
            v4 += __shfl_down_sync(FULL, v4, off);
            v5 += __shfl_down_sync(FULL, v5, off);
            v6 += __shfl_down_sync(FULL, v6, off);
        }
        if (lid == 0) {
            g_S[3 * g + 0] = v0;
            g_S[3 * g + 1] = v1;
            g_S[3 * g + 2] = v2;
            g_R[3 * g + 0] = v3;
            g_R[3 * g + 1] = v4;
            g_R[3 * g + 2] = v5;
            atomicAdd(&g_sumq, v6);
        }
    }
}

// ---------------------------------------------------------------------------
// Kernel 3: pol[g] = S[g] - mean(q) * R[g]
// ---------------------------------------------------------------------------
__global__ void finalize_kernel(float* __restrict__ out, float inv_n) {
    int i = blockIdx.x * blockDim.x + threadIdx.x;
    if (i < NUM_GRAPHS * 3) {
        float mean = g_sumq * inv_n;
        out[i] = fmaf(-mean, g_R[i], g_S[i]);
    }
}

extern "C" void kernel_launch(void* const* d_in, const int* in_sizes, int n_in,
                              void* d_out, int out_size) {
    const float* pos   = (const float*)d_in[0];   // [N,3] float32
    const float* q     = (const float*)d_in[1];   // [N]   float32
    const void*  batch = (const void*)d_in[2];    // [N]   int32 or int64 (sorted)
    float*       out   = (float*)d_out;           // [1024,3] float32
    int n = in_sizes[1];

    boundaries_kernel<<<1, 1024>>>(batch, n);
    polar_main_kernel<<<NUM_GRAPHS, 256>>>(pos, q);
    finalize_kernel<<<(NUM_GRAPHS * 3 + 255) / 256, 256>>>(out, 1.0f / (float)n);
}

// round 3
// speedup vs baseline: 1.2413x; 1.2413x over previous
#include <cuda_runtime.h>

#define NUM_GRAPHS 1024
#define TPB 256

// Scratch (device globals — no allocations allowed)
__device__ float g_S[NUM_GRAPHS * 3];   // sum q_i * r_i per graph
__device__ float g_R[NUM_GRAPHS * 3];   // sum r_i per graph
__device__ float g_Q[NUM_GRAPHS];       // sum q_i per graph
__device__ int   g_done = 0;            // last-block ticket (reset each run by last block)

// ---------------------------------------------------------------------------
// Single fused kernel. One block per graph.
//   prologue: dtype-detect (ballot) + two cooperative 129-ary searches
//   body:     stream segment, 7-way accumulate, unroll x4
//   epilogue: block reduce; last block computes out = S - mean(q)*R
// ---------------------------------------------------------------------------
__global__ __launch_bounds__(TPB) void polar_fused_kernel(
    const float* __restrict__ pos,      // [N,3]
    const float* __restrict__ q,        // [N]
    const void*  __restrict__ batch_raw,// [N] int32 or int64, sorted
    float*       __restrict__ out,      // [1024,3]
    int n, float inv_n)
{
    const int tid = threadIdx.x;
    const int g   = blockIdx.x;

    __shared__ int   sh_is64;
    __shared__ int   sh_lo[2], sh_hi[2];
    __shared__ int   sh_last;
    __shared__ float sh[8][7];
    __shared__ float sh_sumq;

    const int* b32 = (const int*)batch_raw;

    // --- dtype detection: int64 viewed as int32 words is value,0,value,0 (has
    //     decreasing adjacent pairs near tail); sorted int32 is nondecreasing.
    if (tid < 32) {
        int w = n - 34 + tid;                 // pairs (w, w+1), w+1 <= n-1
        int dec = (b32[w + 1] < b32[w]) ? 1 : 0;
        unsigned m = __ballot_sync(0xFFFFFFFFu, dec);
        if (tid == 0) sh_is64 = (m != 0u);
    }
    if (tid == 0) { sh_lo[0] = 0; sh_hi[0] = n; sh_lo[1] = 0; sh_hi[1] = n; }
    __syncthreads();
    const int is64 = sh_is64;

    // --- cooperative 129-ary lower_bound: group 0 -> target g, group 1 -> g+1.
    // Invariant: batch[< lo] < target, batch[>= hi] >= target. 4 rounds always
    // suffice for n <= 129^4-ish (8.4M -> 65k -> 504 -> 3 -> 0).
    {
        const int grp = tid >> 7;             // 0 or 1 (128 threads each)
        const int t   = tid & 127;
        const int target = g + grp;
        #pragma unroll
        for (int r = 0; r < 4; ++r) {
            int lo = sh_lo[grp], hi = sh_hi[grp];
            int size = hi - lo;
            int p = -1, pred = 0;
            if (size > 0) {
                p = lo + (int)(((long long)size * (t + 1)) / 129);
                if (p >= hi) p = hi - 1;
                // values are small nonneg: low word suffices for int64
                int v = is64 ? b32[2 * p] : b32[p];
                pred = (v < target);
            }
            __syncthreads();
            if (size > 0) {
                if (pred) atomicMax(&sh_lo[grp], p + 1);
                else      atomicMin(&sh_hi[grp], p);
            }
            __syncthreads();
        }
    }
    const int start = sh_lo[0];
    const int end   = sh_lo[1];

    // --- stream the segment, unroll x4 for MLP
    float sx = 0.f, sy = 0.f, sz = 0.f;
    float rx = 0.f, ry = 0.f, rz = 0.f;
    float qs = 0.f;

    const float3* __restrict__ pos3 = (const float3*)pos;
    int i = start + tid;
    for (; i + 3 * TPB < end; i += 4 * TPB) {
        float  q0 = q[i];            float  q1 = q[i + TPB];
        float  q2 = q[i + 2 * TPB];  float  q3 = q[i + 3 * TPB];
        float3 p0 = pos3[i];         float3 p1 = pos3[i + TPB];
        float3 p2 = pos3[i + 2*TPB]; float3 p3 = pos3[i + 3*TPB];
        sx = fmaf(q0, p0.x, sx); sy = fmaf(q0, p0.y, sy); sz = fmaf(q0, p0.z, sz);
        sx = fmaf(q1, p1.x, sx); sy = fmaf(q1, p1.y, sy); sz = fmaf(q1, p1.z, sz);
        sx = fmaf(q2, p2.x, sx); sy = fmaf(q2, p2.y, sy); sz = fmaf(q2, p2.z, sz);
        sx = fmaf(q3, p3.x, sx); sy = fmaf(q3, p3.y, sy); sz = fmaf(q3, p3.z, sz);
        rx += (p0.x + p1.x) + (p2.x + p3.x);
        ry += (p0.y + p1.y) + (p2.y + p3.y);
        rz += (p0.z + p1.z) + (p2.z + p3.z);
        qs += (q0 + q1) + (q2 + q3);
    }
    for (; i < end; i += TPB) {
        float  qi = q[i];
        float3 p  = pos3[i];
        sx = fmaf(qi, p.x, sx); sy = fmaf(qi, p.y, sy); sz = fmaf(qi, p.z, sz);
        rx += p.x; ry += p.y; rz += p.z;
        qs += qi;
    }

    // --- block reduction of 7 floats
    const unsigned FULL = 0xFFFFFFFFu;
    #pragma unroll
    for (int off = 16; off > 0; off >>= 1) {
        sx += __shfl_down_sync(FULL, sx, off);
        sy += __shfl_down_sync(FULL, sy, off);
        sz += __shfl_down_sync(FULL, sz, off);
        rx += __shfl_down_sync(FULL, rx, off);
        ry += __shfl_down_sync(FULL, ry, off);
        rz += __shfl_down_sync(FULL, rz, off);
        qs += __shfl_down_sync(FULL, qs, off);
    }
    int wid = tid >> 5, lid = tid & 31;
    if (lid == 0) {
        sh[wid][0] = sx; sh[wid][1] = sy; sh[wid][2] = sz;
        sh[wid][3] = rx; sh[wid][4] = ry; sh[wid][5] = rz;
        sh[wid][6] = qs;
    }
    __syncthreads();
    if (tid == 0) {
        float v0 = 0, v1 = 0, v2 = 0, v3 = 0, v4 = 0, v5 = 0, v6 = 0;
        #pragma unroll
        for (int w = 0; w < TPB / 32; ++w) {
            v0 += sh[w][0]; v1 += sh[w][1]; v2 += sh[w][2];
            v3 += sh[w][3]; v4 += sh[w][4]; v5 += sh[w][5];
            v6 += sh[w][6];
        }
        g_S[3 * g + 0] = v0; g_S[3 * g + 1] = v1; g_S[3 * g + 2] = v2;
        g_R[3 * g + 0] = v3; g_R[3 * g + 1] = v4; g_R[3 * g + 2] = v5;
        g_Q[g] = v6;
        __threadfence();
        int ticket = atomicAdd(&g_done, 1);
        sh_last = (ticket == (int)gridDim.x - 1);
    }
    __syncthreads();

    // --- last block: finalize out = S - mean(q) * R, reset ticket
    if (sh_last) {
        __threadfence();
        float s = 0.f;
        #pragma unroll
        for (int k = tid; k < NUM_GRAPHS; k += TPB) s += g_Q[k];
        #pragma unroll
        for (int off = 16; off > 0; off >>= 1)
            s += __shfl_down_sync(FULL, s, off);
        if (lid == 0) sh[wid][0] = s;
        __syncthreads();
        if (tid == 0) {
            float t = 0.f;
            #pragma unroll
            for (int w = 0; w < TPB / 32; ++w) t += sh[w][0];
            sh_sumq = t;
            g_done = 0;                       // reset for next graph replay
        }
        __syncthreads();
        float mean = sh_sumq * inv_n;
        for (int k = tid; k < NUM_GRAPHS * 3; k += TPB)
            out[k] = fmaf(-mean, g_R[k], g_S[k]);
    }
}

extern "C" void kernel_launch(void* const* d_in, const int* in_sizes, int n_in,
                              void* d_out, int out_size) {
    const float* pos   = (const float*)d_in[0];   // [N,3] float32
    const float* q     = (const float*)d_in[1];   // [N]   float32
    const void*  batch = (const void*)d_in[2];    // [N]   int32/int64 sorted
    float*       out   = (float*)d_out;           // [1024,3] float32
    int n = in_sizes[1];

    polar_fused_kernel<<<NUM_GRAPHS, TPB>>>(pos, q, batch, out, n, 1.0f / (float)n);
}